// round 1
// baseline (speedup 1.0000x reference)
#include <cuda_runtime.h>

// EpochMixer: fused 2-layer transformer over 32768 independent 4-token sequences.
// B=16, T=2048 -> NSEQ=32768 sequences of S=4 tokens (CLS + z0,z1,z2), D=128, H=8, F=512, L=2.
// One block = 16 sequences = 64 tokens, fully resident in SMEM through both layers.
// GEMM microkernel: C[64][128] tile, 256 threads (16x16), 4x8 per-thread tile,
// fma.rn.f32x2 packed fp32 FMAs, weight staged in SMEM in 128x32 chunks.

#define NSEQ   32768
#define GSEQ   16
#define TOK    64
#define DDIM   128
#define FDIM   512
#define NLAYER 2
#define NTHR   256
#define LNEPS  1e-5f

typedef unsigned long long u64;

struct SMem {
    float xs[TOK][DDIM + 4];
    float qs[TOK][DDIM + 4];
    float ks[TOK][DDIM + 4];
    float vs[TOK][DDIM + 4];
    float cb[TOK][DDIM + 4];
    float ws[DDIM][36];
};

__device__ __forceinline__ void fma2(u64 &d, u64 a, u64 b) {
    asm("fma.rn.f32x2 %0, %1, %2, %0;" : "+l"(d) : "l"(a), "l"(b));
}

__device__ __forceinline__ float pairsum(u64 v) {
    float lo = __uint_as_float((unsigned)(v & 0xffffffffULL));
    float hi = __uint_as_float((unsigned)(v >> 32));
    return lo + hi;
}

__device__ __forceinline__ float gelu_exact(float v) {
    return 0.5f * v * (1.0f + erff(v * 0.70710678118654752f));
}

// acc[4][8] += A[64][128] @ Wg^T, where Wg points at W[col0][d0] of a row-major
// weight matrix with row stride ldw (rows = output cols, 128 reduction dims).
__device__ __forceinline__ void mm_acc(
    const float (*A)[DDIM + 4], const float* __restrict__ Wg, int ldw,
    float (*ws)[36], float acc[4][8], int tid)
{
    const int ty = tid >> 4;   // 0..15 -> rows ty, ty+16, ty+32, ty+48
    const int tx = tid & 15;   // 0..15 -> cols tx, tx+16, ..., tx+112

    u64 acc2[4][8];
#pragma unroll
    for (int i = 0; i < 4; i++)
#pragma unroll
        for (int j = 0; j < 8; j++) acc2[i][j] = 0ULL;

#pragma unroll
    for (int dc = 0; dc < 128; dc += 32) {
        __syncthreads();   // previous users of ws done; prior smem writes visible
        // stage weight tile: 128 cols x 32 d = 1024 float4 loads, 4 per thread
#pragma unroll
        for (int u = 0; u < 4; u++) {
            int idx = u * NTHR + tid;          // 0..1023
            int col = idx >> 3;
            int d4  = (idx & 7) << 2;
            *(float4*)&ws[col][d4] =
                *(const float4*)(Wg + (long)col * ldw + dc + d4);
        }
        __syncthreads();
#pragma unroll
        for (int dd = 0; dd < 32; dd += 4) {
            ulonglong2 av[4], wv[8];
#pragma unroll
            for (int i = 0; i < 4; i++)
                av[i] = *(const ulonglong2*)&A[ty + 16 * i][dc + dd];
#pragma unroll
            for (int j = 0; j < 8; j++)
                wv[j] = *(const ulonglong2*)&ws[tx + 16 * j][dd];
#pragma unroll
            for (int i = 0; i < 4; i++)
#pragma unroll
                for (int j = 0; j < 8; j++) {
                    fma2(acc2[i][j], av[i].x, wv[j].x);
                    fma2(acc2[i][j], av[i].y, wv[j].y);
                }
        }
    }
#pragma unroll
    for (int i = 0; i < 4; i++)
#pragma unroll
        for (int j = 0; j < 8; j++) acc[i][j] += pairsum(acc2[i][j]);
}

__device__ __forceinline__ void lnorm(float (*x)[DDIM + 4],
                                      const float* __restrict__ g,
                                      const float* __restrict__ b, int tid)
{
    int w = tid >> 5, lane = tid & 31;
    int c = lane << 2;
#pragma unroll
    for (int r = w; r < TOK; r += 8) {
        float4 v = *(float4*)&x[r][c];
        float s = v.x + v.y + v.z + v.w;
#pragma unroll
        for (int o = 16; o > 0; o >>= 1) s += __shfl_xor_sync(0xffffffffu, s, o);
        float mu = s * (1.0f / 128.0f);
        float d0 = v.x - mu, d1 = v.y - mu, d2 = v.z - mu, d3 = v.w - mu;
        float q = d0 * d0 + d1 * d1 + d2 * d2 + d3 * d3;
#pragma unroll
        for (int o = 16; o > 0; o >>= 1) q += __shfl_xor_sync(0xffffffffu, q, o);
        float inv = rsqrtf(q * (1.0f / 128.0f) + LNEPS);
        v.x = d0 * inv * g[c + 0] + b[c + 0];
        v.y = d1 * inv * g[c + 1] + b[c + 1];
        v.z = d2 * inv * g[c + 2] + b[c + 2];
        v.w = d3 * inv * g[c + 3] + b[c + 3];
        *(float4*)&x[r][c] = v;
    }
}

__global__ void __launch_bounds__(NTHR, 1)
epochmixer_kernel(const float* __restrict__ z0, const float* __restrict__ z1,
                  const float* __restrict__ z2, const float* __restrict__ cls,
                  const float* __restrict__ Wqkv, const float* __restrict__ bqkv,
                  const float* __restrict__ Wo,  const float* __restrict__ bo,
                  const float* __restrict__ W1,  const float* __restrict__ b1,
                  const float* __restrict__ W2,  const float* __restrict__ b2,
                  const float* __restrict__ ln1g, const float* __restrict__ ln1b,
                  const float* __restrict__ ln2g, const float* __restrict__ ln2b,
                  float* __restrict__ out)
{
    extern __shared__ char smraw[];
    SMem &sm = *reinterpret_cast<SMem*>(smraw);

    const int tid  = threadIdx.x;
    const int ty   = tid >> 4;
    const int tx   = tid & 15;
    const int seq0 = blockIdx.x * GSEQ;

    // ---- load tokens: row = g*4+s; s=0 CLS, s=1..3 -> z_{s-1}[seq0+g] ----
#pragma unroll
    for (int u = 0; u < 8; u++) {
        int idx = u * NTHR + tid;          // 0..2047
        int row = idx >> 5;                // 0..63
        int c4  = (idx & 31) << 2;
        int g   = row >> 2, s = row & 3;
        float4 v;
        if (s == 0) {
            v = *(const float4*)(cls + c4);
        } else {
            const float* zp = (s == 1) ? z0 : (s == 2) ? z1 : z2;
            v = *(const float4*)(zp + (long)(seq0 + g) * DDIM + c4);
        }
        *(float4*)&sm.xs[row][c4] = v;
    }
    __syncthreads();

    for (int l = 0; l < NLAYER; l++) {
        const float* Wqkv_l = Wqkv + (long)l * 3 * DDIM * DDIM;
        const float* bqkv_l = bqkv + l * 3 * DDIM;
        const float* Wo_l   = Wo   + (long)l * DDIM * DDIM;
        const float* bo_l   = bo   + l * DDIM;
        const float* W1_l   = W1   + (long)l * FDIM * DDIM;
        const float* b1_l   = b1   + l * FDIM;
        const float* W2_l   = W2   + (long)l * DDIM * FDIM;
        const float* b2_l   = b2   + l * DDIM;

        // ---- QKV projections ----
        for (int p = 0; p < 3; p++) {
            float acc[4][8];
#pragma unroll
            for (int i = 0; i < 4; i++)
#pragma unroll
                for (int j = 0; j < 8; j++) acc[i][j] = 0.0f;
            mm_acc(sm.xs, Wqkv_l + (long)p * DDIM * DDIM, DDIM, sm.ws, acc, tid);
            float (*dst)[DDIM + 4] = (p == 0) ? sm.qs : (p == 1) ? sm.ks : sm.vs;
            const float* bp = bqkv_l + p * DDIM;
#pragma unroll
            for (int i = 0; i < 4; i++)
#pragma unroll
                for (int j = 0; j < 8; j++) {
                    int row = ty + 16 * i, col = tx + 16 * j;
                    dst[row][col] = acc[i][j] + bp[col];
                }
        }
        __syncthreads();

        // ---- attention: one thread per (local seq, head); S=4, dh=16 ----
        if (tid < 128) {
            int g = tid >> 3, h = tid & 7;
            int r0 = g * 4, co = h * 16;
            float sc[4][4];
#pragma unroll
            for (int i = 0; i < 4; i++)
#pragma unroll
                for (int j = 0; j < 4; j++) {
                    float s = 0.0f;
#pragma unroll
                    for (int e = 0; e < 16; e++)
                        s += sm.qs[r0 + i][co + e] * sm.ks[r0 + j][co + e];
                    sc[i][j] = s * 0.25f;   // 1/sqrt(16)
                }
#pragma unroll
            for (int i = 0; i < 4; i++) {
                float m = sc[i][0];
#pragma unroll
                for (int j = 1; j < 4; j++) m = fmaxf(m, sc[i][j]);
                float den = 0.0f;
#pragma unroll
                for (int j = 0; j < 4; j++) {
                    sc[i][j] = expf(sc[i][j] - m);
                    den += sc[i][j];
                }
                float inv = 1.0f / den;
#pragma unroll
                for (int j = 0; j < 4; j++) sc[i][j] *= inv;
            }
#pragma unroll
            for (int i = 0; i < 4; i++)
#pragma unroll
                for (int e = 0; e < 16; e++) {
                    float o = 0.0f;
#pragma unroll
                    for (int j = 0; j < 4; j++)
                        o += sc[i][j] * sm.vs[r0 + j][co + e];
                    sm.cb[r0 + i][co + e] = o;
                }
        }
        __syncthreads();

        // ---- output projection + residual, then LN1 ----
        {
            float acc[4][8];
#pragma unroll
            for (int i = 0; i < 4; i++)
#pragma unroll
                for (int j = 0; j < 8; j++) acc[i][j] = 0.0f;
            mm_acc(sm.cb, Wo_l, DDIM, sm.ws, acc, tid);
#pragma unroll
            for (int i = 0; i < 4; i++)
#pragma unroll
                for (int j = 0; j < 8; j++) {
                    int row = ty + 16 * i, col = tx + 16 * j;
                    sm.xs[row][col] += acc[i][j] + bo_l[col];
                }
        }
        __syncthreads();
        lnorm(sm.xs, ln1g + l * DDIM, ln1b + l * DDIM, tid);
        __syncthreads();

        // ---- FFN: chunk F=512 into 4 x 128; h=gelu(x@W1^T) ; ff += h@W2chunk^T ----
        float facc[4][8];
#pragma unroll
        for (int i = 0; i < 4; i++)
#pragma unroll
            for (int j = 0; j < 8; j++) facc[i][j] = 0.0f;

        for (int fc = 0; fc < FDIM; fc += 128) {
            float hacc[4][8];
#pragma unroll
            for (int i = 0; i < 4; i++)
#pragma unroll
                for (int j = 0; j < 8; j++) hacc[i][j] = 0.0f;
            mm_acc(sm.xs, W1_l + (long)fc * DDIM, DDIM, sm.ws, hacc, tid);
            const float* b1p = b1_l + fc;
#pragma unroll
            for (int i = 0; i < 4; i++)
#pragma unroll
                for (int j = 0; j < 8; j++) {
                    int row = ty + 16 * i, col = tx + 16 * j;
                    sm.cb[row][col] = gelu_exact(hacc[i][j] + b1p[col]);
                }
            // barrier inside next mm_acc orders cb writes before reads
            mm_acc(sm.cb, W2_l + fc, FDIM, sm.ws, facc, tid);
        }
#pragma unroll
        for (int i = 0; i < 4; i++)
#pragma unroll
            for (int j = 0; j < 8; j++) {
                int row = ty + 16 * i, col = tx + 16 * j;
                sm.xs[row][col] += facc[i][j] + b2_l[col];
            }
        __syncthreads();
        lnorm(sm.xs, ln2g + l * DDIM, ln2b + l * DDIM, tid);
        __syncthreads();
    }

    // ---- write CLS tokens: out[seq0+g][0:128] = xs[4g][:] ----
#pragma unroll
    for (int u = 0; u < 2; u++) {
        int idx = u * NTHR + tid;          // 0..511
        int g   = idx >> 5;
        int c4  = (idx & 31) << 2;
        *(float4*)(out + (long)(seq0 + g) * DDIM + c4) = *(float4*)&sm.xs[g * 4][c4];
    }
}

extern "C" void kernel_launch(void* const* d_in, const int* in_sizes, int n_in,
                              void* d_out, int out_size)
{
    (void)in_sizes; (void)n_in; (void)out_size;
    const float* z0   = (const float*)d_in[0];
    const float* z1   = (const float*)d_in[1];
    const float* z2   = (const float*)d_in[2];
    const float* cls  = (const float*)d_in[3];
    const float* Wqkv = (const float*)d_in[4];
    const float* bqkv = (const float*)d_in[5];
    const float* Wo   = (const float*)d_in[6];
    const float* bo   = (const float*)d_in[7];
    const float* W1   = (const float*)d_in[8];
    const float* b1   = (const float*)d_in[9];
    const float* W2   = (const float*)d_in[10];
    const float* b2   = (const float*)d_in[11];
    const float* ln1g = (const float*)d_in[12];
    const float* ln1b = (const float*)d_in[13];
    const float* ln2g = (const float*)d_in[14];
    const float* ln2b = (const float*)d_in[15];
    float* out = (float*)d_out;

    cudaFuncSetAttribute(epochmixer_kernel,
                         cudaFuncAttributeMaxDynamicSharedMemorySize,
                         (int)sizeof(SMem));
    epochmixer_kernel<<<NSEQ / GSEQ, NTHR, sizeof(SMem)>>>(
        z0, z1, z2, cls, Wqkv, bqkv, Wo, bo, W1, b1, W2, b2,
        ln1g, ln1b, ln2g, ln2b, out);
}